// round 2
// baseline (speedup 1.0000x reference)
#include <cuda_runtime.h>
#include <cuda_bf16.h>
#include <cstdint>

#define NN 50000
#define EE 800000
#define INC 128
#define HID 256
#define OUTC 15

// ---------------- scratch (static device allocations; no cudaMalloc) --------
__device__ __align__(16) float g_acc[(size_t)NN * HID];   // aggregation accumulator
__device__ __align__(16) float g_h1 [(size_t)NN * HID];   // hidden buffer A
__device__ __align__(16) float g_h2 [(size_t)NN * HID];   // hidden buffer B
__device__ __align__(16) float g_cnt[NN];                 // in-degree (float)
__device__ __align__(16) float g_inv[NN];                 // 1/max(deg,1)

// ---------------- small utility kernels -------------------------------------
__global__ void zero_kernel(float* __restrict__ p, int n) {
    int i = blockIdx.x * blockDim.x + threadIdx.x;
    int stride = gridDim.x * blockDim.x;
    for (; i < n; i += stride) p[i] = 0.0f;
}

__global__ void deg_kernel(const int* __restrict__ ei, float* __restrict__ cnt) {
    int e = blockIdx.x * blockDim.x + threadIdx.x;
    if (e < EE) {
        int dst = ei[EE + e];
        atomicAdd(&cnt[dst], 1.0f);
    }
}

__global__ void inv_kernel(const float* __restrict__ cnt, float* __restrict__ inv) {
    int i = blockIdx.x * blockDim.x + threadIdx.x;
    if (i < NN) inv[i] = 1.0f / fmaxf(cnt[i], 1.0f);
}

// ---------------- edge scatter: acc[dst] += x[src] ---------------------------
// One thread per (edge, 4-float chunk). Consecutive threads share an edge, so
// edge-index loads are warp-broadcast and feature loads are coalesced.
template<int LOGCH>  // CH = 1<<LOGCH float4 chunks per row; d = 4*CH
__global__ void scatter_kernel(const float* __restrict__ x,
                               const int* __restrict__ ei,
                               float* __restrict__ acc) {
    const int CH = 1 << LOGCH;       // float4 chunks per row
    const int d  = CH * 4;           // feature dim
    int idx = blockIdx.x * blockDim.x + threadIdx.x;
    if (idx >= (EE << LOGCH)) return;
    int e = idx >> LOGCH;
    int c = (idx & (CH - 1)) << 2;   // float offset within row
    int s  = ei[e];
    int dt = ei[EE + e];
    const float4 v = *reinterpret_cast<const float4*>(x + (size_t)s * d + c);
    float* p = acc + (size_t)dt * d + c;
    asm volatile("red.global.add.v4.f32 [%0], {%1, %2, %3, %4};"
                 :: "l"(p), "f"(v.x), "f"(v.y), "f"(v.z), "f"(v.w) : "memory");
}

// ---------------- fused SAGE layer GEMM --------------------------------------
// out[M,256] = relu( (acc[M,K] * inv[row]) @ Wl[K,256] + X[M,K] @ Wr[K,256] + b[256] )
// 128x128 tile, BK=8, 256 threads, 8x8 micro-tile per thread.
#define BM 128
#define BN 128
#define BK 8
__global__ void __launch_bounds__(256)
sage_gemm_kernel(const float* __restrict__ Aacc, const float* __restrict__ inv,
                 const float* __restrict__ X,
                 const float* __restrict__ Wl, const float* __restrict__ Wr,
                 const float* __restrict__ bias, float* __restrict__ out,
                 int M, int K) {
    __shared__ float As[BK][BM];
    __shared__ float Bs[BK][BN];

    const int tid = threadIdx.x;
    const int m0 = blockIdx.x * BM;
    const int n0 = blockIdx.y * BN;
    const int tx = tid & 15;   // 0..15 -> 8 cols each
    const int ty = tid >> 4;   // 0..15 -> 8 rows each

    // A-tile load mapping: 128 rows x 8 cols = 256 float4 loads (one per thread)
    const int alr = tid >> 1;          // row in tile
    const int alc = (tid & 1) * 4;     // col (0 or 4)
    // B-tile load mapping: 8 rows x 128 cols = 256 float4 loads
    const int blk = tid >> 5;          // k-row 0..7
    const int bln = (tid & 31) * 4;    // col 0..124

    float acc[8][8];
    #pragma unroll
    for (int i = 0; i < 8; i++)
        #pragma unroll
        for (int j = 0; j < 8; j++) acc[i][j] = 0.0f;

    #pragma unroll 1
    for (int pass = 0; pass < 2; ++pass) {
        const float* A = pass ? X : Aacc;
        const float* B = pass ? Wr : Wl;
        #pragma unroll 1
        for (int k0 = 0; k0 < K; k0 += BK) {
            const int arow = m0 + alr;
            float4 av = make_float4(0.f, 0.f, 0.f, 0.f);
            if (arow < M) {
                av = *reinterpret_cast<const float4*>(A + (size_t)arow * K + k0 + alc);
                if (pass == 0) {
                    const float s = inv[arow];
                    av.x *= s; av.y *= s; av.z *= s; av.w *= s;
                }
            }
            const float4 bv = *reinterpret_cast<const float4*>(
                B + (size_t)(k0 + blk) * HID + n0 + bln);
            __syncthreads();   // previous tile fully consumed
            As[alc + 0][alr] = av.x;
            As[alc + 1][alr] = av.y;
            As[alc + 2][alr] = av.z;
            As[alc + 3][alr] = av.w;
            *reinterpret_cast<float4*>(&Bs[blk][bln]) = bv;
            __syncthreads();

            #pragma unroll
            for (int kk = 0; kk < BK; kk++) {
                float a[8], b[8];
                const float4 a0 = *reinterpret_cast<const float4*>(&As[kk][ty * 8]);
                const float4 a1 = *reinterpret_cast<const float4*>(&As[kk][ty * 8 + 4]);
                a[0]=a0.x; a[1]=a0.y; a[2]=a0.z; a[3]=a0.w;
                a[4]=a1.x; a[5]=a1.y; a[6]=a1.z; a[7]=a1.w;
                const float4 b0 = *reinterpret_cast<const float4*>(&Bs[kk][tx * 8]);
                const float4 b1 = *reinterpret_cast<const float4*>(&Bs[kk][tx * 8 + 4]);
                b[0]=b0.x; b[1]=b0.y; b[2]=b0.z; b[3]=b0.w;
                b[4]=b1.x; b[5]=b1.y; b[6]=b1.z; b[7]=b1.w;
                #pragma unroll
                for (int i = 0; i < 8; i++)
                    #pragma unroll
                    for (int j = 0; j < 8; j++)
                        acc[i][j] = fmaf(a[i], b[j], acc[i][j]);
            }
        }
    }

    // epilogue: bias + relu
    #pragma unroll
    for (int i = 0; i < 8; i++) {
        const int row = m0 + ty * 8 + i;
        if (row >= M) continue;
        #pragma unroll
        for (int j = 0; j < 8; j += 4) {
            const int col = n0 + tx * 8 + j;
            float4 v;
            v.x = fmaxf(acc[i][j + 0] + bias[col + 0], 0.f);
            v.y = fmaxf(acc[i][j + 1] + bias[col + 1], 0.f);
            v.z = fmaxf(acc[i][j + 2] + bias[col + 2], 0.f);
            v.w = fmaxf(acc[i][j + 3] + bias[col + 3], 0.f);
            *reinterpret_cast<float4*>(out + (size_t)row * HID + col) = v;
        }
    }
}

// ---------------- output head: out[N,15] = h[N,256] @ Wo[256,15] + bo --------
__global__ void __launch_bounds__(256)
out_kernel(const float* __restrict__ h, const float* __restrict__ Wo,
           const float* __restrict__ bo, float* __restrict__ out) {
    __shared__ float sW[HID * OUTC];
    __shared__ float sb[OUTC];
    const int tid = threadIdx.x;
    for (int i = tid; i < HID * OUTC; i += 256) sW[i] = Wo[i];
    if (tid < OUTC) sb[tid] = bo[tid];
    __syncthreads();

    const int warp = tid >> 5;
    const int lane = tid & 31;
    const int row = blockIdx.x * 8 + warp;
    if (row >= NN) return;

    float a15[OUTC];
    #pragma unroll
    for (int j = 0; j < OUTC; j++) a15[j] = 0.0f;

    #pragma unroll
    for (int k = lane; k < HID; k += 32) {
        const float a = h[(size_t)row * HID + k];
        const float* w = &sW[k * OUTC];
        #pragma unroll
        for (int j = 0; j < OUTC; j++) a15[j] = fmaf(a, w[j], a15[j]);
    }
    #pragma unroll
    for (int j = 0; j < OUTC; j++) {
        #pragma unroll
        for (int off = 16; off > 0; off >>= 1)
            a15[j] += __shfl_down_sync(0xffffffffu, a15[j], off);
    }
    if (lane == 0) {
        #pragma unroll
        for (int j = 0; j < OUTC; j++)
            out[(size_t)row * OUTC + j] = a15[j] + sb[j];
    }
}

// ---------------- launch ------------------------------------------------------
extern "C" void kernel_launch(void* const* d_in, const int* in_sizes, int n_in,
                              void* d_out, int out_size) {
    const float* x   = (const float*)d_in[0];
    const int*   ei  = (const int*)d_in[1];     // int32: JAX x64-disabled downcast
    const float* Wl1 = (const float*)d_in[2];
    const float* bl1 = (const float*)d_in[3];
    const float* Wr1 = (const float*)d_in[4];
    const float* Wl2 = (const float*)d_in[5];
    const float* bl2 = (const float*)d_in[6];
    const float* Wr2 = (const float*)d_in[7];
    const float* Wl3 = (const float*)d_in[8];
    const float* bl3 = (const float*)d_in[9];
    const float* Wr3 = (const float*)d_in[10];
    const float* Wo  = (const float*)d_in[11];
    const float* bo  = (const float*)d_in[12];
    float* out = (float*)d_out;

    float *acc, *h1, *h2, *cnt, *inv;
    cudaGetSymbolAddress((void**)&acc, g_acc);
    cudaGetSymbolAddress((void**)&h1,  g_h1);
    cudaGetSymbolAddress((void**)&h2,  g_h2);
    cudaGetSymbolAddress((void**)&cnt, g_cnt);
    cudaGetSymbolAddress((void**)&inv, g_inv);

    const dim3 gemm_grid((NN + BM - 1) / BM, HID / BN);  // (391, 2)

    // degrees (shared across all 3 layers)
    zero_kernel<<<512, 256>>>(cnt, NN);
    deg_kernel<<<(EE + 255) / 256, 256>>>(ei, cnt);
    inv_kernel<<<(NN + 255) / 256, 256>>>(cnt, inv);

    // ---- layer 1 (d = 128) ----
    zero_kernel<<<4096, 256>>>(acc, NN * INC);
    scatter_kernel<5><<<(EE * 32) / 256, 256>>>(x, ei, acc);
    sage_gemm_kernel<<<gemm_grid, 256>>>(acc, inv, x, Wl1, Wr1, bl1, h1, NN, INC);

    // ---- layer 2 (d = 256) ----
    zero_kernel<<<8192, 256>>>(acc, NN * HID);
    scatter_kernel<6><<<(EE * 64) / 256, 256>>>(h1, ei, acc);
    sage_gemm_kernel<<<gemm_grid, 256>>>(acc, inv, h1, Wl2, Wr2, bl2, h2, NN, HID);

    // ---- layer 3 (d = 256) ----
    zero_kernel<<<8192, 256>>>(acc, NN * HID);
    scatter_kernel<6><<<(EE * 64) / 256, 256>>>(h2, ei, acc);
    sage_gemm_kernel<<<gemm_grid, 256>>>(acc, inv, h2, Wl3, Wr3, bl3, h1, NN, HID);

    // ---- output head ----
    out_kernel<<<(NN + 7) / 8, 256>>>(h1, Wo, bo, out);
}

// round 4
// speedup vs baseline: 1.4124x; 1.4124x over previous
#include <cuda_runtime.h>
#include <cuda_bf16.h>
#include <cstdint>

#define NN 50000
#define EE 800000
#define INC 128
#define HID 256
#define OUTC 15

// ---------------- scratch (static; no cudaMalloc) ----------------------------
__device__ __align__(16) float g_acc[(size_t)NN * HID];
__device__ __align__(16) float g_h1 [(size_t)NN * HID];
__device__ __align__(16) float g_h2 [(size_t)NN * HID];
__device__ __align__(16) float g_cnt[NN];
__device__ __align__(16) float g_inv[NN];
__device__ __align__(16) __nv_bfloat16 g_mhi[(size_t)NN * HID];
__device__ __align__(16) __nv_bfloat16 g_mlo[(size_t)NN * HID];
__device__ __align__(16) __nv_bfloat16 g_ahi[(size_t)NN * HID];
__device__ __align__(16) __nv_bfloat16 g_alo[(size_t)NN * HID];
__device__ __align__(16) __nv_bfloat16 g_bhi[(size_t)NN * HID];
__device__ __align__(16) __nv_bfloat16 g_blo[(size_t)NN * HID];
__device__ __align__(16) __nv_bfloat16 g_wthi[6 * HID * HID];
__device__ __align__(16) __nv_bfloat16 g_wtlo[6 * HID * HID];

// ---------------- mma helpers (sm_80+ path; no sm_100a features) -------------
__device__ __forceinline__ void ldsm_x4(uint32_t& r0, uint32_t& r1,
                                        uint32_t& r2, uint32_t& r3, uint32_t addr) {
    asm volatile("ldmatrix.sync.aligned.m8n8.x4.shared.b16 {%0,%1,%2,%3}, [%4];"
                 : "=r"(r0), "=r"(r1), "=r"(r2), "=r"(r3) : "r"(addr));
}
__device__ __forceinline__ void mma_bf16(float* d, const uint32_t* a, const uint32_t* b) {
    asm volatile("mma.sync.aligned.m16n8k16.row.col.f32.bf16.bf16.f32 "
                 "{%0,%1,%2,%3}, {%4,%5,%6,%7}, {%8,%9}, {%0,%1,%2,%3};"
                 : "+f"(d[0]), "+f"(d[1]), "+f"(d[2]), "+f"(d[3])
                 : "r"(a[0]), "r"(a[1]), "r"(a[2]), "r"(a[3]), "r"(b[0]), "r"(b[1]));
}

// ---------------- small utility kernels --------------------------------------
__global__ void zero_kernel(float* __restrict__ p, int n) {
    int i = blockIdx.x * blockDim.x + threadIdx.x;
    int stride = gridDim.x * blockDim.x;
    for (; i < n; i += stride) p[i] = 0.0f;
}

__global__ void deg_kernel(const int* __restrict__ ei, float* __restrict__ cnt) {
    int e = blockIdx.x * blockDim.x + threadIdx.x;
    if (e < EE) atomicAdd(&cnt[ei[EE + e]], 1.0f);
}

__global__ void inv_kernel(const float* __restrict__ cnt, float* __restrict__ inv) {
    int i = blockIdx.x * blockDim.x + threadIdx.x;
    if (i < NN) inv[i] = 1.0f / fmaxf(cnt[i], 1.0f);
}

// split fp32 -> (hi, lo) bf16, optional per-row scale by inv[row]
__global__ void split_kernel(const float* __restrict__ in, const float* __restrict__ inv,
                             __nv_bfloat16* __restrict__ hi, __nv_bfloat16* __restrict__ lo,
                             int n4, int logd) {
    int i = blockIdx.x * blockDim.x + threadIdx.x;
    if (i >= n4) return;
    float4 a = reinterpret_cast<const float4*>(in)[i];
    if (inv) {
        float s = inv[(i << 2) >> logd];
        a.x *= s; a.y *= s; a.z *= s; a.w *= s;
    }
    __nv_bfloat16 h0 = __float2bfloat16_rn(a.x), h1 = __float2bfloat16_rn(a.y);
    __nv_bfloat16 h2 = __float2bfloat16_rn(a.z), h3 = __float2bfloat16_rn(a.w);
    __nv_bfloat16 l0 = __float2bfloat16_rn(a.x - __bfloat162float(h0));
    __nv_bfloat16 l1 = __float2bfloat16_rn(a.y - __bfloat162float(h1));
    __nv_bfloat16 l2 = __float2bfloat16_rn(a.z - __bfloat162float(h2));
    __nv_bfloat16 l3 = __float2bfloat16_rn(a.w - __bfloat162float(h3));
    __nv_bfloat162 p;
    p.x = h0; p.y = h1; reinterpret_cast<__nv_bfloat162*>(hi)[i * 2]     = p;
    p.x = h2; p.y = h3; reinterpret_cast<__nv_bfloat162*>(hi)[i * 2 + 1] = p;
    p.x = l0; p.y = l1; reinterpret_cast<__nv_bfloat162*>(lo)[i * 2]     = p;
    p.x = l2; p.y = l3; reinterpret_cast<__nv_bfloat162*>(lo)[i * 2 + 1] = p;
}

// transpose + split weights: W[K,256] -> Wt_hi/lo[256,K]
__global__ void wtsplit_kernel(const float* __restrict__ W,
                               __nv_bfloat16* __restrict__ thi,
                               __nv_bfloat16* __restrict__ tlo, int K) {
    int idx = blockIdx.x * 256 + threadIdx.x;
    if (idx >= K * 256) return;
    int n = idx & 255, k = idx >> 8;
    float v = W[(size_t)k * 256 + n];
    __nv_bfloat16 h = __float2bfloat16_rn(v);
    thi[(size_t)n * K + k] = h;
    tlo[(size_t)n * K + k] = __float2bfloat16_rn(v - __bfloat162float(h));
}

// ---------------- edge scatter: acc[dst] += x[src] ---------------------------
template<int LOGCH>
__global__ void scatter_kernel(const float* __restrict__ x,
                               const int* __restrict__ ei,
                               float* __restrict__ acc) {
    const int CH = 1 << LOGCH;
    const int d  = CH * 4;
    int idx = blockIdx.x * blockDim.x + threadIdx.x;
    if (idx >= (EE << LOGCH)) return;
    int e = idx >> LOGCH;
    int c = (idx & (CH - 1)) << 2;
    int s  = ei[e];
    int dt = ei[EE + e];
    const float4 v = *reinterpret_cast<const float4*>(x + (size_t)s * d + c);
    float* p = acc + (size_t)dt * d + c;
    asm volatile("red.global.add.v4.f32 [%0], {%1, %2, %3, %4};"
                 :: "l"(p), "f"(v.x), "f"(v.y), "f"(v.z), "f"(v.w) : "memory");
}

// ---------------- bf16 mma.sync SAGE GEMM ------------------------------------
// D[128,128] = (mhi+mlo)@(wl)^T + (shi+slo)@(wr)^T ; hi/lo 3-term split.
// CTA: 256 thr = 8 warps (2m x 4n), warp tile 64x32. K-chunks of 32 in smem,
// 80B row stride (odd 16B-stride => conflict-free ldmatrix).
#define ROWB 80
__global__ void __launch_bounds__(256, 2)
sage_hmma_kernel(const __nv_bfloat16* __restrict__ mhi, const __nv_bfloat16* __restrict__ mlo,
                 const __nv_bfloat16* __restrict__ shi, const __nv_bfloat16* __restrict__ slo,
                 const __nv_bfloat16* __restrict__ wlhi, const __nv_bfloat16* __restrict__ wllo,
                 const __nv_bfloat16* __restrict__ wrhi, const __nv_bfloat16* __restrict__ wrlo,
                 const float* __restrict__ bias,
                 float* __restrict__ hout,
                 __nv_bfloat16* __restrict__ hhi, __nv_bfloat16* __restrict__ hlo,
                 int K) {
    __shared__ __align__(16) unsigned char sAhi[128 * ROWB];
    __shared__ __align__(16) unsigned char sAlo[128 * ROWB];
    __shared__ __align__(16) unsigned char sBhi[128 * ROWB];
    __shared__ __align__(16) unsigned char sBlo[128 * ROWB];
    __shared__ float sbias[128];

    const int tid  = threadIdx.x;
    const int wid  = tid >> 5;
    const int lane = tid & 31;
    const int wm   = wid & 1;        // 0..1 : 64-row slice
    const int wn   = wid >> 1;       // 0..3 : 32-col slice
    const int m0   = blockIdx.x * 128;
    const int n0   = blockIdx.y * 128;

    if (tid < 128) sbias[tid] = bias[n0 + tid];

    const uint32_t uAhi = (uint32_t)__cvta_generic_to_shared(sAhi);
    const uint32_t uAlo = (uint32_t)__cvta_generic_to_shared(sAlo);
    const uint32_t uBhi = (uint32_t)__cvta_generic_to_shared(sBhi);
    const uint32_t uBlo = (uint32_t)__cvta_generic_to_shared(sBlo);

    float acc[4][4][4];
    #pragma unroll
    for (int i = 0; i < 4; i++)
        #pragma unroll
        for (int j = 0; j < 4; j++)
            #pragma unroll
            for (int k = 0; k < 4; k++) acc[i][j][k] = 0.0f;

    // ldmatrix lane->address components
    const int a_row = (lane & 15);          // row within 16
    const int a_u   = (lane >> 4);          // k8 half 0/1
    const int b_row = (lane & 7) + ((lane & 16) >> 1);  // n within 16
    const int b_u   = (lane >> 3) & 1;                  // k8 half

    #pragma unroll 1
    for (int pass = 0; pass < 2; ++pass) {
        const __nv_bfloat16* Ahi = pass ? shi : mhi;
        const __nv_bfloat16* Alo = pass ? slo : mlo;
        const __nv_bfloat16* Bhi = pass ? wrhi : wlhi;
        const __nv_bfloat16* Blo = pass ? wrlo : wllo;
        #pragma unroll 1
        for (int kc = 0; kc < K; kc += 32) {
            __syncthreads();   // previous chunk fully consumed
            // stage A (128 rows x 32 k), 512 16B units
            #pragma unroll
            for (int i = tid; i < 512; i += 256) {
                int r = i >> 2, u = i & 3;
                uint4 vh = make_uint4(0, 0, 0, 0), vl = make_uint4(0, 0, 0, 0);
                int gr = m0 + r;
                if (gr < NN) {
                    size_t off = (size_t)gr * K + kc + u * 8;
                    vh = *reinterpret_cast<const uint4*>(Ahi + off);
                    vl = *reinterpret_cast<const uint4*>(Alo + off);
                }
                int so = r * ROWB + u * 16;
                *reinterpret_cast<uint4*>(sAhi + so) = vh;
                *reinterpret_cast<uint4*>(sAlo + so) = vl;
            }
            // stage B (128 n-rows x 32 k)
            #pragma unroll
            for (int i = tid; i < 512; i += 256) {
                int r = i >> 2, u = i & 3;
                size_t off = (size_t)(n0 + r) * K + kc + u * 8;
                *reinterpret_cast<uint4*>(sBhi + r * ROWB + u * 16) =
                    *reinterpret_cast<const uint4*>(Bhi + off);
                *reinterpret_cast<uint4*>(sBlo + r * ROWB + u * 16) =
                    *reinterpret_cast<const uint4*>(Blo + off);
            }
            __syncthreads();

            #pragma unroll
            for (int s = 0; s < 2; ++s) {
                // A fragments for this k16 step
                uint32_t ah[4][4], al[4][4];
                const int au = s * 2 + a_u;
                #pragma unroll
                for (int mf = 0; mf < 4; ++mf) {
                    uint32_t off = (uint32_t)((wm * 64 + mf * 16 + a_row) * ROWB + au * 16);
                    ldsm_x4(ah[mf][0], ah[mf][1], ah[mf][2], ah[mf][3], uAhi + off);
                    ldsm_x4(al[mf][0], al[mf][1], al[mf][2], al[mf][3], uAlo + off);
                }
                const int bu = s * 2 + b_u;
                #pragma unroll
                for (int nfp = 0; nfp < 2; ++nfp) {
                    uint32_t off = (uint32_t)((wn * 32 + nfp * 16 + b_row) * ROWB + bu * 16);
                    uint32_t bh[4], bl[4];
                    ldsm_x4(bh[0], bh[1], bh[2], bh[3], uBhi + off);
                    ldsm_x4(bl[0], bl[1], bl[2], bl[3], uBlo + off);
                    #pragma unroll
                    for (int mf = 0; mf < 4; ++mf) {
                        #pragma unroll
                        for (int nf2 = 0; nf2 < 2; ++nf2) {
                            float* d = acc[mf][nfp * 2 + nf2];
                            mma_bf16(d, ah[mf], &bh[nf2 * 2]);
                            mma_bf16(d, ah[mf], &bl[nf2 * 2]);
                            mma_bf16(d, al[mf], &bh[nf2 * 2]);
                        }
                    }
                }
            }
        }
    }

    // epilogue: bias + relu; store fp32 + (hi,lo) bf16
    #pragma unroll
    for (int mf = 0; mf < 4; ++mf) {
        #pragma unroll
        for (int nf = 0; nf < 4; ++nf) {
            const int lc = wn * 32 + nf * 8 + (lane & 3) * 2;
            const float b0 = sbias[lc], b1 = sbias[lc + 1];
            #pragma unroll
            for (int half = 0; half < 2; ++half) {
                const int row = m0 + wm * 64 + mf * 16 + (lane >> 2) + half * 8;
                if (row < NN) {
                    float v0 = fmaxf(acc[mf][nf][half * 2 + 0] + b0, 0.0f);
                    float v1 = fmaxf(acc[mf][nf][half * 2 + 1] + b1, 0.0f);
                    size_t o = (size_t)row * 256 + n0 + lc;
                    *reinterpret_cast<float2*>(hout + o) = make_float2(v0, v1);
                    __nv_bfloat16 h0 = __float2bfloat16_rn(v0);
                    __nv_bfloat16 h1 = __float2bfloat16_rn(v1);
                    __nv_bfloat162 ph, pl;
                    ph.x = h0; ph.y = h1;
                    pl.x = __float2bfloat16_rn(v0 - __bfloat162float(h0));
                    pl.y = __float2bfloat16_rn(v1 - __bfloat162float(h1));
                    *reinterpret_cast<__nv_bfloat162*>(hhi + o) = ph;
                    *reinterpret_cast<__nv_bfloat162*>(hlo + o) = pl;
                }
            }
        }
    }
}

// ---------------- output head ------------------------------------------------
__global__ void __launch_bounds__(256)
out_kernel(const float* __restrict__ h, const float* __restrict__ Wo,
           const float* __restrict__ bo, float* __restrict__ out) {
    __shared__ float sW[HID * OUTC];
    __shared__ float sb[OUTC];
    const int tid = threadIdx.x;
    for (int i = tid; i < HID * OUTC; i += 256) sW[i] = Wo[i];
    if (tid < OUTC) sb[tid] = bo[tid];
    __syncthreads();

    const int warp = tid >> 5;
    const int lane = tid & 31;
    const int row = blockIdx.x * 8 + warp;
    if (row >= NN) return;

    float a15[OUTC];
    #pragma unroll
    for (int j = 0; j < OUTC; j++) a15[j] = 0.0f;
    #pragma unroll
    for (int k = lane; k < HID; k += 32) {
        const float a = h[(size_t)row * HID + k];
        const float* w = &sW[k * OUTC];
        #pragma unroll
        for (int j = 0; j < OUTC; j++) a15[j] = fmaf(a, w[j], a15[j]);
    }
    #pragma unroll
    for (int j = 0; j < OUTC; j++) {
        #pragma unroll
        for (int off = 16; off > 0; off >>= 1)
            a15[j] += __shfl_down_sync(0xffffffffu, a15[j], off);
    }
    if (lane == 0) {
        #pragma unroll
        for (int j = 0; j < OUTC; j++)
            out[(size_t)row * OUTC + j] = a15[j] + sb[j];
    }
}

// ---------------- launch ------------------------------------------------------
extern "C" void kernel_launch(void* const* d_in, const int* in_sizes, int n_in,
                              void* d_out, int out_size) {
    const float* x   = (const float*)d_in[0];
    const int*   ei  = (const int*)d_in[1];
    const float* Wl1 = (const float*)d_in[2];
    const float* bl1 = (const float*)d_in[3];
    const float* Wr1 = (const float*)d_in[4];
    const float* Wl2 = (const float*)d_in[5];
    const float* bl2 = (const float*)d_in[6];
    const float* Wr2 = (const float*)d_in[7];
    const float* Wl3 = (const float*)d_in[8];
    const float* bl3 = (const float*)d_in[9];
    const float* Wr3 = (const float*)d_in[10];
    const float* Wo  = (const float*)d_in[11];
    const float* bo  = (const float*)d_in[12];
    float* out = (float*)d_out;

    float *acc, *h1, *h2, *cnt, *inv;
    __nv_bfloat16 *mhi, *mlo, *ahi, *alo, *bhi, *blo, *wthi, *wtlo;
    cudaGetSymbolAddress((void**)&acc, g_acc);
    cudaGetSymbolAddress((void**)&h1,  g_h1);
    cudaGetSymbolAddress((void**)&h2,  g_h2);
    cudaGetSymbolAddress((void**)&cnt, g_cnt);
    cudaGetSymbolAddress((void**)&inv, g_inv);
    cudaGetSymbolAddress((void**)&mhi, g_mhi);
    cudaGetSymbolAddress((void**)&mlo, g_mlo);
    cudaGetSymbolAddress((void**)&ahi, g_ahi);
    cudaGetSymbolAddress((void**)&alo, g_alo);
    cudaGetSymbolAddress((void**)&bhi, g_bhi);
    cudaGetSymbolAddress((void**)&blo, g_blo);
    cudaGetSymbolAddress((void**)&wthi, g_wthi);
    cudaGetSymbolAddress((void**)&wtlo, g_wtlo);

    const int MT = (NN + 127) / 128;   // 391
    const dim3 gg(MT, 2);
    const int WSLOT = HID * HID;       // 65536

    // degrees
    zero_kernel<<<512, 256>>>(cnt, NN);
    deg_kernel<<<(EE + 255) / 256, 256>>>(ei, cnt);
    inv_kernel<<<(NN + 255) / 256, 256>>>(cnt, inv);

    // weight transpose + split
    wtsplit_kernel<<<INC, 256>>>(Wl1, wthi + 0 * WSLOT, wtlo + 0 * WSLOT, INC);
    wtsplit_kernel<<<INC, 256>>>(Wr1, wthi + 1 * WSLOT, wtlo + 1 * WSLOT, INC);
    wtsplit_kernel<<<HID, 256>>>(Wl2, wthi + 2 * WSLOT, wtlo + 2 * WSLOT, HID);
    wtsplit_kernel<<<HID, 256>>>(Wr2, wthi + 3 * WSLOT, wtlo + 3 * WSLOT, HID);
    wtsplit_kernel<<<HID, 256>>>(Wl3, wthi + 4 * WSLOT, wtlo + 4 * WSLOT, HID);
    wtsplit_kernel<<<HID, 256>>>(Wr3, wthi + 5 * WSLOT, wtlo + 5 * WSLOT, HID);

    // x -> (ahi, alo)
    split_kernel<<<(NN * INC / 4 + 255) / 256, 256>>>(x, nullptr, ahi, alo, NN * INC / 4, 0);

    // ---- layer 1 (K = 128) ----
    zero_kernel<<<4096, 256>>>(acc, NN * INC);
    scatter_kernel<5><<<(EE * 32) / 256, 256>>>(x, ei, acc);
    split_kernel<<<(NN * INC / 4 + 255) / 256, 256>>>(acc, inv, mhi, mlo, NN * INC / 4, 7);
    sage_hmma_kernel<<<gg, 256>>>(mhi, mlo, ahi, alo,
        wthi + 0 * WSLOT, wtlo + 0 * WSLOT, wthi + 1 * WSLOT, wtlo + 1 * WSLOT,
        bl1, h1, bhi, blo, INC);

    // ---- layer 2 (K = 256) ----
    zero_kernel<<<8192, 256>>>(acc, NN * HID);
    scatter_kernel<6><<<(EE * 64) / 256, 256>>>(h1, ei, acc);
    split_kernel<<<(NN * HID / 4 + 255) / 256, 256>>>(acc, inv, mhi, mlo, NN * HID / 4, 8);
    sage_hmma_kernel<<<gg, 256>>>(mhi, mlo, bhi, blo,
        wthi + 2 * WSLOT, wtlo + 2 * WSLOT, wthi + 3 * WSLOT, wtlo + 3 * WSLOT,
        bl2, h2, ahi, alo, HID);

    // ---- layer 3 (K = 256) ----
    zero_kernel<<<8192, 256>>>(acc, NN * HID);
    scatter_kernel<6><<<(EE * 64) / 256, 256>>>(h2, ei, acc);
    split_kernel<<<(NN * HID / 4 + 255) / 256, 256>>>(acc, inv, mhi, mlo, NN * HID / 4, 8);
    sage_hmma_kernel<<<gg, 256>>>(mhi, mlo, ahi, alo,
        wthi + 4 * WSLOT, wtlo + 4 * WSLOT, wthi + 5 * WSLOT, wtlo + 5 * WSLOT,
        bl3, h1, bhi, blo, HID);

    // ---- output head ----
    out_kernel<<<(NN + 7) / 8, 256>>>(h1, Wo, bo, out);
}

// round 5
// speedup vs baseline: 1.9939x; 1.4117x over previous
#include <cuda_runtime.h>
#include <cuda_bf16.h>
#include <cstdint>

#define NN 50000
#define EE 800000
#define INC 128
#define HID 256
#define OUTC 15

// ---------------- scratch (static; no cudaMalloc) ----------------------------
__device__ __align__(16) int g_deg[NN];
__device__ __align__(16) int g_off[NN + 1];
__device__ __align__(16) int g_cur[NN];
__device__ __align__(16) int g_srcl[EE];
__device__ __align__(16) __nv_bfloat16 g_mhi[(size_t)NN * HID];
__device__ __align__(16) __nv_bfloat16 g_mlo[(size_t)NN * HID];
__device__ __align__(16) __nv_bfloat16 g_ahi[(size_t)NN * HID];
__device__ __align__(16) __nv_bfloat16 g_alo[(size_t)NN * HID];
__device__ __align__(16) __nv_bfloat16 g_bhi[(size_t)NN * HID];
__device__ __align__(16) __nv_bfloat16 g_blo[(size_t)NN * HID];
__device__ __align__(16) __nv_bfloat16 g_wthi[6 * HID * HID];
__device__ __align__(16) __nv_bfloat16 g_wtlo[6 * HID * HID];

// ---------------- mma helpers (sm_80+ path) ----------------------------------
__device__ __forceinline__ void ldsm_x4(uint32_t& r0, uint32_t& r1,
                                        uint32_t& r2, uint32_t& r3, uint32_t addr) {
    asm volatile("ldmatrix.sync.aligned.m8n8.x4.shared.b16 {%0,%1,%2,%3}, [%4];"
                 : "=r"(r0), "=r"(r1), "=r"(r2), "=r"(r3) : "r"(addr));
}
__device__ __forceinline__ void mma_bf16(float* d, const uint32_t* a, const uint32_t* b) {
    asm volatile("mma.sync.aligned.m16n8k16.row.col.f32.bf16.bf16.f32 "
                 "{%0,%1,%2,%3}, {%4,%5,%6,%7}, {%8,%9}, {%0,%1,%2,%3};"
                 : "+f"(d[0]), "+f"(d[1]), "+f"(d[2]), "+f"(d[3])
                 : "r"(a[0]), "r"(a[1]), "r"(a[2]), "r"(a[3]), "r"(b[0]), "r"(b[1]));
}

// ---------------- CSR build --------------------------------------------------
__global__ void zero_int_kernel(int* __restrict__ p, int n) {
    int i = blockIdx.x * blockDim.x + threadIdx.x;
    if (i < n) p[i] = 0;
}

__global__ void deg_kernel(const int* __restrict__ ei, int* __restrict__ deg) {
    int e = blockIdx.x * blockDim.x + threadIdx.x;
    if (e < EE) atomicAdd(&deg[ei[EE + e]], 1);
}

// single-block exclusive scan over NN degrees -> off, cur; off[NN]=EE
__global__ void scan_kernel(const int* __restrict__ deg, int* __restrict__ off,
                            int* __restrict__ cur) {
    __shared__ int part[1024];
    const int tid = threadIdx.x;
    const int CH = (NN + 1023) / 1024;   // 49
    const int base = tid * CH;
    int s = 0;
    for (int i = 0; i < CH; i++) {
        int idx = base + i;
        if (idx < NN) s += deg[idx];
    }
    part[tid] = s;
    __syncthreads();
    for (int d = 1; d < 1024; d <<= 1) {
        int v = 0;
        if (tid >= d) v = part[tid - d];
        __syncthreads();
        if (tid >= d) part[tid] += v;
        __syncthreads();
    }
    int run = (tid == 0) ? 0 : part[tid - 1];
    for (int i = 0; i < CH; i++) {
        int idx = base + i;
        if (idx < NN) {
            off[idx] = run;
            cur[idx] = run;
            run += deg[idx];
        }
    }
    if (tid == 1023) off[NN] = EE;
}

__global__ void fill_kernel(const int* __restrict__ ei, int* __restrict__ cur,
                            int* __restrict__ srcl) {
    int e = blockIdx.x * blockDim.x + threadIdx.x;
    if (e < EE) {
        int pos = atomicAdd(&cur[ei[EE + e]], 1);
        srcl[pos] = ei[e];
    }
}

// ---------------- splits -----------------------------------------------------
// fp32 -> (hi, lo) bf16 (x features only)
__global__ void split_kernel(const float* __restrict__ in,
                             __nv_bfloat16* __restrict__ hi, __nv_bfloat16* __restrict__ lo,
                             int n4) {
    int i = blockIdx.x * blockDim.x + threadIdx.x;
    if (i >= n4) return;
    float4 a = reinterpret_cast<const float4*>(in)[i];
    __nv_bfloat16 h0 = __float2bfloat16_rn(a.x), h1 = __float2bfloat16_rn(a.y);
    __nv_bfloat16 h2 = __float2bfloat16_rn(a.z), h3 = __float2bfloat16_rn(a.w);
    __nv_bfloat162 p;
    p.x = h0; p.y = h1; reinterpret_cast<__nv_bfloat162*>(hi)[i * 2]     = p;
    p.x = h2; p.y = h3; reinterpret_cast<__nv_bfloat162*>(hi)[i * 2 + 1] = p;
    p.x = __float2bfloat16_rn(a.x - __bfloat162float(h0));
    p.y = __float2bfloat16_rn(a.y - __bfloat162float(h1));
    reinterpret_cast<__nv_bfloat162*>(lo)[i * 2] = p;
    p.x = __float2bfloat16_rn(a.z - __bfloat162float(h2));
    p.y = __float2bfloat16_rn(a.w - __bfloat162float(h3));
    reinterpret_cast<__nv_bfloat162*>(lo)[i * 2 + 1] = p;
}

// transpose + split weights: W[K,256] -> Wt_hi/lo[256,K]
__global__ void wtsplit_kernel(const float* __restrict__ W,
                               __nv_bfloat16* __restrict__ thi,
                               __nv_bfloat16* __restrict__ tlo, int K) {
    int idx = blockIdx.x * 256 + threadIdx.x;
    if (idx >= K * 256) return;
    int n = idx & 255, k = idx >> 8;
    float v = W[(size_t)k * 256 + n];
    __nv_bfloat16 h = __float2bfloat16_rn(v);
    thi[(size_t)n * K + k] = h;
    tlo[(size_t)n * K + k] = __float2bfloat16_rn(v - __bfloat162float(h));
}

// ---------------- gather mean (CSR) ------------------------------------------
// warp per node; lane handles D/32 floats. Epilogue: *inv, split, write bf16.
template<int D>
__global__ void __launch_bounds__(256)
gather_f32_kernel(const float* __restrict__ x, const int* __restrict__ off,
                  const int* __restrict__ srcl,
                  __nv_bfloat16* __restrict__ mhi, __nv_bfloat16* __restrict__ mlo) {
    const int node = blockIdx.x * 8 + (threadIdx.x >> 5);
    if (node >= NN) return;
    const int lane = threadIdx.x & 31;
    const int s0 = off[node], s1 = off[node + 1];
    const int F = D / 32;                // 4 or 8
    float acc[F];
    #pragma unroll
    for (int j = 0; j < F; j++) acc[j] = 0.0f;

    int i = s0;
    for (; i + 1 < s1; i += 2) {
        const float4* p0 = reinterpret_cast<const float4*>(x + (size_t)srcl[i] * D + lane * F);
        const float4* p1 = reinterpret_cast<const float4*>(x + (size_t)srcl[i + 1] * D + lane * F);
        #pragma unroll
        for (int u = 0; u < F / 4; u++) {
            float4 v0 = p0[u], v1 = p1[u];
            acc[u * 4 + 0] += v0.x + v1.x;
            acc[u * 4 + 1] += v0.y + v1.y;
            acc[u * 4 + 2] += v0.z + v1.z;
            acc[u * 4 + 3] += v0.w + v1.w;
        }
    }
    if (i < s1) {
        const float4* p0 = reinterpret_cast<const float4*>(x + (size_t)srcl[i] * D + lane * F);
        #pragma unroll
        for (int u = 0; u < F / 4; u++) {
            float4 v0 = p0[u];
            acc[u * 4 + 0] += v0.x;
            acc[u * 4 + 1] += v0.y;
            acc[u * 4 + 2] += v0.z;
            acc[u * 4 + 3] += v0.w;
        }
    }

    const float invd = 1.0f / fmaxf((float)(s1 - s0), 1.0f);
    uint32_t ph[F / 2], pl[F / 2];
    #pragma unroll
    for (int u = 0; u < F / 2; u++) {
        float a0 = acc[2 * u] * invd, a1 = acc[2 * u + 1] * invd;
        __nv_bfloat162 th, tl;
        th.x = __float2bfloat16_rn(a0);
        th.y = __float2bfloat16_rn(a1);
        tl.x = __float2bfloat16_rn(a0 - __bfloat162float(th.x));
        tl.y = __float2bfloat16_rn(a1 - __bfloat162float(th.y));
        ph[u] = *reinterpret_cast<uint32_t*>(&th);
        pl[u] = *reinterpret_cast<uint32_t*>(&tl);
    }
    const size_t o = (size_t)node * D + lane * F;
    if (F == 4) {
        *reinterpret_cast<uint2*>(mhi + o) = make_uint2(ph[0], ph[1]);
        *reinterpret_cast<uint2*>(mlo + o) = make_uint2(pl[0], pl[1]);
    } else {
        *reinterpret_cast<uint4*>(mhi + o) = make_uint4(ph[0], ph[1], ph[2], ph[3]);
        *reinterpret_cast<uint4*>(mlo + o) = make_uint4(pl[0], pl[1], pl[2], pl[3]);
    }
}

__device__ __forceinline__ void add_pair8(float* acc, uint4 vh, uint4 vl) {
    const uint32_t h[4] = {vh.x, vh.y, vh.z, vh.w};
    const uint32_t l[4] = {vl.x, vl.y, vl.z, vl.w};
    #pragma unroll
    for (int u = 0; u < 4; u++) {
        float2 fh = __bfloat1622float2(*reinterpret_cast<const __nv_bfloat162*>(&h[u]));
        float2 fl = __bfloat1622float2(*reinterpret_cast<const __nv_bfloat162*>(&l[u]));
        acc[u * 2 + 0] += fh.x + fl.x;
        acc[u * 2 + 1] += fh.y + fl.y;
    }
}

// gather over bf16 hi/lo input (D = 256)
__global__ void __launch_bounds__(256)
gather_bf16_kernel(const __nv_bfloat16* __restrict__ hhi, const __nv_bfloat16* __restrict__ hlo,
                   const int* __restrict__ off, const int* __restrict__ srcl,
                   __nv_bfloat16* __restrict__ mhi, __nv_bfloat16* __restrict__ mlo) {
    const int node = blockIdx.x * 8 + (threadIdx.x >> 5);
    if (node >= NN) return;
    const int lane = threadIdx.x & 31;
    const int s0 = off[node], s1 = off[node + 1];
    float acc[8];
    #pragma unroll
    for (int j = 0; j < 8; j++) acc[j] = 0.0f;

    for (int i = s0; i < s1; i++) {
        const size_t ro = (size_t)srcl[i] * HID + lane * 8;
        uint4 vh = *reinterpret_cast<const uint4*>(hhi + ro);
        uint4 vl = *reinterpret_cast<const uint4*>(hlo + ro);
        add_pair8(acc, vh, vl);
    }

    const float invd = 1.0f / fmaxf((float)(s1 - s0), 1.0f);
    uint32_t ph[4], pl[4];
    #pragma unroll
    for (int u = 0; u < 4; u++) {
        float a0 = acc[2 * u] * invd, a1 = acc[2 * u + 1] * invd;
        __nv_bfloat162 th, tl;
        th.x = __float2bfloat16_rn(a0);
        th.y = __float2bfloat16_rn(a1);
        tl.x = __float2bfloat16_rn(a0 - __bfloat162float(th.x));
        tl.y = __float2bfloat16_rn(a1 - __bfloat162float(th.y));
        ph[u] = *reinterpret_cast<uint32_t*>(&th);
        pl[u] = *reinterpret_cast<uint32_t*>(&tl);
    }
    const size_t o = (size_t)node * HID + lane * 8;
    *reinterpret_cast<uint4*>(mhi + o) = make_uint4(ph[0], ph[1], ph[2], ph[3]);
    *reinterpret_cast<uint4*>(mlo + o) = make_uint4(pl[0], pl[1], pl[2], pl[3]);
}

// ---------------- bf16 mma.sync SAGE GEMM ------------------------------------
#define ROWB 80
__global__ void __launch_bounds__(256, 2)
sage_hmma_kernel(const __nv_bfloat16* __restrict__ mhi, const __nv_bfloat16* __restrict__ mlo,
                 const __nv_bfloat16* __restrict__ shi, const __nv_bfloat16* __restrict__ slo,
                 const __nv_bfloat16* __restrict__ wlhi, const __nv_bfloat16* __restrict__ wllo,
                 const __nv_bfloat16* __restrict__ wrhi, const __nv_bfloat16* __restrict__ wrlo,
                 const float* __restrict__ bias,
                 __nv_bfloat16* __restrict__ hhi, __nv_bfloat16* __restrict__ hlo,
                 int K) {
    __shared__ __align__(16) unsigned char sAhi[128 * ROWB];
    __shared__ __align__(16) unsigned char sAlo[128 * ROWB];
    __shared__ __align__(16) unsigned char sBhi[128 * ROWB];
    __shared__ __align__(16) unsigned char sBlo[128 * ROWB];
    __shared__ float sbias[128];

    const int tid  = threadIdx.x;
    const int wid  = tid >> 5;
    const int lane = tid & 31;
    const int wm   = wid & 1;
    const int wn   = wid >> 1;
    const int m0   = blockIdx.x * 128;
    const int n0   = blockIdx.y * 128;

    if (tid < 128) sbias[tid] = bias[n0 + tid];

    const uint32_t uAhi = (uint32_t)__cvta_generic_to_shared(sAhi);
    const uint32_t uAlo = (uint32_t)__cvta_generic_to_shared(sAlo);
    const uint32_t uBhi = (uint32_t)__cvta_generic_to_shared(sBhi);
    const uint32_t uBlo = (uint32_t)__cvta_generic_to_shared(sBlo);

    float acc[4][4][4];
    #pragma unroll
    for (int i = 0; i < 4; i++)
        #pragma unroll
        for (int j = 0; j < 4; j++)
            #pragma unroll
            for (int k = 0; k < 4; k++) acc[i][j][k] = 0.0f;

    const int a_row = (lane & 15);
    const int a_u   = (lane >> 4);
    const int b_row = (lane & 7) + ((lane & 16) >> 1);
    const int b_u   = (lane >> 3) & 1;

    #pragma unroll 1
    for (int pass = 0; pass < 2; ++pass) {
        const __nv_bfloat16* Ahi = pass ? shi : mhi;
        const __nv_bfloat16* Alo = pass ? slo : mlo;
        const __nv_bfloat16* Bhi = pass ? wrhi : wlhi;
        const __nv_bfloat16* Blo = pass ? wrlo : wllo;
        #pragma unroll 1
        for (int kc = 0; kc < K; kc += 32) {
            __syncthreads();
            #pragma unroll
            for (int i = tid; i < 512; i += 256) {
                int r = i >> 2, u = i & 3;
                uint4 vh = make_uint4(0, 0, 0, 0), vl = make_uint4(0, 0, 0, 0);
                int gr = m0 + r;
                if (gr < NN) {
                    size_t off = (size_t)gr * K + kc + u * 8;
                    vh = *reinterpret_cast<const uint4*>(Ahi + off);
                    vl = *reinterpret_cast<const uint4*>(Alo + off);
                }
                int so = r * ROWB + u * 16;
                *reinterpret_cast<uint4*>(sAhi + so) = vh;
                *reinterpret_cast<uint4*>(sAlo + so) = vl;
            }
            #pragma unroll
            for (int i = tid; i < 512; i += 256) {
                int r = i >> 2, u = i & 3;
                size_t off = (size_t)(n0 + r) * K + kc + u * 8;
                *reinterpret_cast<uint4*>(sBhi + r * ROWB + u * 16) =
                    *reinterpret_cast<const uint4*>(Bhi + off);
                *reinterpret_cast<uint4*>(sBlo + r * ROWB + u * 16) =
                    *reinterpret_cast<const uint4*>(Blo + off);
            }
            __syncthreads();

            #pragma unroll
            for (int s = 0; s < 2; ++s) {
                uint32_t ah[4][4], al[4][4];
                const int au = s * 2 + a_u;
                #pragma unroll
                for (int mf = 0; mf < 4; ++mf) {
                    uint32_t off = (uint32_t)((wm * 64 + mf * 16 + a_row) * ROWB + au * 16);
                    ldsm_x4(ah[mf][0], ah[mf][1], ah[mf][2], ah[mf][3], uAhi + off);
                    ldsm_x4(al[mf][0], al[mf][1], al[mf][2], al[mf][3], uAlo + off);
                }
                const int bu = s * 2 + b_u;
                #pragma unroll
                for (int nfp = 0; nfp < 2; ++nfp) {
                    uint32_t off = (uint32_t)((wn * 32 + nfp * 16 + b_row) * ROWB + bu * 16);
                    uint32_t bh[4], bl[4];
                    ldsm_x4(bh[0], bh[1], bh[2], bh[3], uBhi + off);
                    ldsm_x4(bl[0], bl[1], bl[2], bl[3], uBlo + off);
                    #pragma unroll
                    for (int mf = 0; mf < 4; ++mf) {
                        #pragma unroll
                        for (int nf2 = 0; nf2 < 2; ++nf2) {
                            float* d = acc[mf][nfp * 2 + nf2];
                            mma_bf16(d, ah[mf], &bh[nf2 * 2]);
                            mma_bf16(d, ah[mf], &bl[nf2 * 2]);
                            mma_bf16(d, al[mf], &bh[nf2 * 2]);
                        }
                    }
                }
            }
        }
    }

    // epilogue: bias + relu; store (hi, lo) bf16 only
    #pragma unroll
    for (int mf = 0; mf < 4; ++mf) {
        #pragma unroll
        for (int nf = 0; nf < 4; ++nf) {
            const int lc = wn * 32 + nf * 8 + (lane & 3) * 2;
            const float b0 = sbias[lc], b1 = sbias[lc + 1];
            #pragma unroll
            for (int half = 0; half < 2; ++half) {
                const int row = m0 + wm * 64 + mf * 16 + (lane >> 2) + half * 8;
                if (row < NN) {
                    float v0 = fmaxf(acc[mf][nf][half * 2 + 0] + b0, 0.0f);
                    float v1 = fmaxf(acc[mf][nf][half * 2 + 1] + b1, 0.0f);
                    size_t o = (size_t)row * 256 + n0 + lc;
                    __nv_bfloat16 h0 = __float2bfloat16_rn(v0);
                    __nv_bfloat16 h1 = __float2bfloat16_rn(v1);
                    __nv_bfloat162 ph, pl;
                    ph.x = h0; ph.y = h1;
                    pl.x = __float2bfloat16_rn(v0 - __bfloat162float(h0));
                    pl.y = __float2bfloat16_rn(v1 - __bfloat162float(h1));
                    *reinterpret_cast<__nv_bfloat162*>(hhi + o) = ph;
                    *reinterpret_cast<__nv_bfloat162*>(hlo + o) = pl;
                }
            }
        }
    }
}

// ---------------- output head ------------------------------------------------
__global__ void __launch_bounds__(256)
out_kernel(const __nv_bfloat16* __restrict__ hhi, const __nv_bfloat16* __restrict__ hlo,
           const float* __restrict__ Wo, const float* __restrict__ bo,
           float* __restrict__ out) {
    __shared__ float sW[HID * OUTC];
    __shared__ float sb[OUTC];
    const int tid = threadIdx.x;
    for (int i = tid; i < HID * OUTC; i += 256) sW[i] = Wo[i];
    if (tid < OUTC) sb[tid] = bo[tid];
    __syncthreads();

    const int warp = tid >> 5;
    const int lane = tid & 31;
    const int row = blockIdx.x * 8 + warp;
    if (row >= NN) return;

    const size_t ro = (size_t)row * HID + lane * 8;
    uint4 vh = *reinterpret_cast<const uint4*>(hhi + ro);
    uint4 vl = *reinterpret_cast<const uint4*>(hlo + ro);
    float v[8];
    {
        const uint32_t h[4] = {vh.x, vh.y, vh.z, vh.w};
        const uint32_t l[4] = {vl.x, vl.y, vl.z, vl.w};
        #pragma unroll
        for (int u = 0; u < 4; u++) {
            float2 fh = __bfloat1622float2(*reinterpret_cast<const __nv_bfloat162*>(&h[u]));
            float2 fl = __bfloat1622float2(*reinterpret_cast<const __nv_bfloat162*>(&l[u]));
            v[u * 2 + 0] = fh.x + fl.x;
            v[u * 2 + 1] = fh.y + fl.y;
        }
    }

    float a15[OUTC];
    #pragma unroll
    for (int j = 0; j < OUTC; j++) a15[j] = 0.0f;
    #pragma unroll
    for (int t = 0; t < 8; t++) {
        const int k = lane * 8 + t;
        const float* w = &sW[k * OUTC];
        #pragma unroll
        for (int j = 0; j < OUTC; j++) a15[j] = fmaf(v[t], w[j], a15[j]);
    }
    #pragma unroll
    for (int j = 0; j < OUTC; j++) {
        #pragma unroll
        for (int off = 16; off > 0; off >>= 1)
            a15[j] += __shfl_down_sync(0xffffffffu, a15[j], off);
    }
    if (lane == 0) {
        #pragma unroll
        for (int j = 0; j < OUTC; j++)
            out[(size_t)row * OUTC + j] = a15[j] + sb[j];
    }
}

// ---------------- launch ------------------------------------------------------
extern "C" void kernel_launch(void* const* d_in, const int* in_sizes, int n_in,
                              void* d_out, int out_size) {
    const float* x   = (const float*)d_in[0];
    const int*   ei  = (const int*)d_in[1];
    const float* Wl1 = (const float*)d_in[2];
    const float* bl1 = (const float*)d_in[3];
    const float* Wr1 = (const float*)d_in[4];
    const float* Wl2 = (const float*)d_in[5];
    const float* bl2 = (const float*)d_in[6];
    const float* Wr2 = (const float*)d_in[7];
    const float* Wl3 = (const float*)d_in[8];
    const float* bl3 = (const float*)d_in[9];
    const float* Wr3 = (const float*)d_in[10];
    const float* Wo  = (const float*)d_in[11];
    const float* bo  = (const float*)d_in[12];
    float* out = (float*)d_out;

    int *deg, *off, *cur, *srcl;
    __nv_bfloat16 *mhi, *mlo, *ahi, *alo, *bhi, *blo, *wthi, *wtlo;
    cudaGetSymbolAddress((void**)&deg, g_deg);
    cudaGetSymbolAddress((void**)&off, g_off);
    cudaGetSymbolAddress((void**)&cur, g_cur);
    cudaGetSymbolAddress((void**)&srcl, g_srcl);
    cudaGetSymbolAddress((void**)&mhi, g_mhi);
    cudaGetSymbolAddress((void**)&mlo, g_mlo);
    cudaGetSymbolAddress((void**)&ahi, g_ahi);
    cudaGetSymbolAddress((void**)&alo, g_alo);
    cudaGetSymbolAddress((void**)&bhi, g_bhi);
    cudaGetSymbolAddress((void**)&blo, g_blo);
    cudaGetSymbolAddress((void**)&wthi, g_wthi);
    cudaGetSymbolAddress((void**)&wtlo, g_wtlo);

    const int MT = (NN + 127) / 128;   // 391
    const dim3 gg(MT, 2);
    const int WSLOT = HID * HID;       // 65536
    const int GB = (NN + 7) / 8;       // gather blocks (8 warps each)

    // ---- CSR build (per call; order-nondeterminism only perturbs fp32 sums) --
    zero_int_kernel<<<(NN + 255) / 256, 256>>>(deg, NN);
    deg_kernel<<<(EE + 255) / 256, 256>>>(ei, deg);
    scan_kernel<<<1, 1024>>>(deg, off, cur);
    fill_kernel<<<(EE + 255) / 256, 256>>>(ei, cur, srcl);

    // weight transpose + split
    wtsplit_kernel<<<INC, 256>>>(Wl1, wthi + 0 * WSLOT, wtlo + 0 * WSLOT, INC);
    wtsplit_kernel<<<INC, 256>>>(Wr1, wthi + 1 * WSLOT, wtlo + 1 * WSLOT, INC);
    wtsplit_kernel<<<HID, 256>>>(Wl2, wthi + 2 * WSLOT, wtlo + 2 * WSLOT, HID);
    wtsplit_kernel<<<HID, 256>>>(Wr2, wthi + 3 * WSLOT, wtlo + 3 * WSLOT, HID);
    wtsplit_kernel<<<HID, 256>>>(Wl3, wthi + 4 * WSLOT, wtlo + 4 * WSLOT, HID);
    wtsplit_kernel<<<HID, 256>>>(Wr3, wthi + 5 * WSLOT, wtlo + 5 * WSLOT, HID);

    // x -> (ahi, alo)
    split_kernel<<<(NN * INC / 4 + 255) / 256, 256>>>(x, ahi, alo, NN * INC / 4);

    // ---- layer 1 (K = 128) ----
    gather_f32_kernel<INC><<<GB, 256>>>(x, off, srcl, mhi, mlo);
    sage_hmma_kernel<<<gg, 256>>>(mhi, mlo, ahi, alo,
        wthi + 0 * WSLOT, wtlo + 0 * WSLOT, wthi + 1 * WSLOT, wtlo + 1 * WSLOT,
        bl1, bhi, blo, INC);

    // ---- layer 2 (K = 256) ----
    gather_bf16_kernel<<<GB, 256>>>(bhi, blo, off, srcl, mhi, mlo);
    sage_hmma_kernel<<<gg, 256>>>(mhi, mlo, bhi, blo,
        wthi + 2 * WSLOT, wtlo + 2 * WSLOT, wthi + 3 * WSLOT, wtlo + 3 * WSLOT,
        bl2, ahi, alo, HID);

    // ---- layer 3 (K = 256) ----
    gather_bf16_kernel<<<GB, 256>>>(ahi, alo, off, srcl, mhi, mlo);
    sage_hmma_kernel<<<gg, 256>>>(mhi, mlo, ahi, alo,
        wthi + 4 * WSLOT, wtlo + 4 * WSLOT, wthi + 5 * WSLOT, wtlo + 5 * WSLOT,
        bl3, bhi, blo, HID);

    // ---- output head ----
    out_kernel<<<GB, 256>>>(bhi, blo, Wo, bo, out);
}